// round 5
// baseline (speedup 1.0000x reference)
#include <cuda_runtime.h>

#define SEQ    512
#define NROW   2048
#define NELEM  (NROW*64)

typedef unsigned long long u64;

// ---------------- f32x2 helpers ----------------
__device__ __forceinline__ u64 ffma2(u64 a, u64 b, u64 c) {
    u64 d; asm("fma.rn.f32x2 %0, %1, %2, %3;" : "=l"(d) : "l"(a), "l"(b), "l"(c)); return d;
}
__device__ __forceinline__ u64 mul2(u64 a, u64 b) {
    u64 d; asm("mul.rn.f32x2 %0, %1, %2;" : "=l"(d) : "l"(a), "l"(b)); return d;
}
__device__ __forceinline__ u64 add2(u64 a, u64 b) {
    u64 d; asm("add.rn.f32x2 %0, %1, %2;" : "=l"(d) : "l"(a), "l"(b)); return d;
}
__device__ __forceinline__ u64 dup2(float x) {
    u64 d; asm("mov.b64 %0, {%1, %1};" : "=l"(d) : "f"(x)); return d;
}
__device__ __forceinline__ float2 unpk(u64 a) {
    float2 f; asm("mov.b64 {%0, %1}, %2;" : "=f"(f.x), "=f"(f.y) : "l"(a)); return f;
}
__device__ __forceinline__ float ex2f(float x) {
    float r; asm("ex2.approx.f32 %0, %1;" : "=f"(r) : "f"(x)); return r;
}

// ---------------- device scratch ----------------
__device__ float g_y   [NELEM];
__device__ float g_ys  [NELEM];
__device__ float g_kbuf[6][NELEM];
__device__ float g_q   [NELEM];   // [B,H,S,8]
__device__ float g_kT  [NELEM];   // [B,H,8,S]  (transposed K)
__device__ float g_v   [NELEM];   // [B,H,S,8]
__device__ float g_attp[NELEM];   // [B,S,64]

__device__ unsigned          g_cnt;
__device__ volatile unsigned g_gen;

__constant__ float d_C[6][5] = {
    {0.f,0.f,0.f,0.f,0.f},
    {(float)(0.25*0.25), 0.f,0.f,0.f,0.f},
    {(float)(0.25*3.0/32.0), (float)(0.25*9.0/32.0), 0.f,0.f,0.f},
    {(float)(0.25*1932.0/2197.0), (float)(0.25*-7200.0/2197.0),
     (float)(0.25*7296.0/2197.0), 0.f,0.f},
    {(float)(0.25*439.0/216.0), (float)(0.25*-8.0),
     (float)(0.25*3680.0/513.0), (float)(0.25*-845.0/4104.0), 0.f},
    {(float)(0.25*-8.0/27.0), (float)(0.25*2.0),
     (float)(0.25*-3544.0/2565.0), (float)(0.25*1859.0/4104.0),
     (float)(0.25*-11.0/40.0)}
};
__constant__ float d_B[6] = {
    (float)(0.25*16.0/135.0), 0.f,
    (float)(0.25*6656.0/12825.0),
    (float)(0.25*28561.0/56430.0),
    (float)(0.25*-9.0/50.0),
    (float)(0.25*2.0/55.0)
};

// ---------------- grid barrier ----------------
__device__ __forceinline__ void gsync(unsigned& gen) {
    __syncthreads();
    if (threadIdx.x == 0) {
        __threadfence();
        if (atomicAdd(&g_cnt, 1u) == gridDim.x - 1) {
            g_cnt = 0;
            __threadfence();
            g_gen = gen + 1;
        } else {
            while (g_gen == gen) __nanosleep(32);
            __threadfence();
        }
    }
    __syncthreads();
    gen++;
}

// ---------------- QKV projection from an 8x64 smem tile ----------------
__device__ __forceinline__ void qkv_from_smem(
        const float* __restrict__ ys_s, int row0,
        const float* __restrict__ Wq, const float* __restrict__ bq,
        const float* __restrict__ Wk, const float* __restrict__ bk,
        const float* __restrict__ Wv, const float* __restrict__ bv) {
    const int t = threadIdx.x;
    if (t >= 192) return;
    const int mat = t >> 6;
    const int w6  = t & 63;
    const int cq  = w6 >> 2;
    const int rp  = w6 & 3;
    const int c4  = cq * 4;
    const float* W  = (mat == 0) ? Wq : (mat == 1) ? Wk : Wv;
    const float* bb = (mat == 0) ? bq : (mat == 1) ? bk : bv;

    u64 a0x = 0, a0y = 0, a1x = 0, a1y = 0;
    const float* z0 = ys_s + (2 * rp) * 64;
    const float* z1 = z0 + 64;
#pragma unroll 8
    for (int kk = 0; kk < 64; kk++) {
        ulonglong2 w = *(const ulonglong2*)(W + kk * 64 + c4);
        u64 d0 = dup2(z0[kk]), d1 = dup2(z1[kk]);
        a0x = ffma2(d0, w.x, a0x); a0y = ffma2(d0, w.y, a0y);
        a1x = ffma2(d1, w.x, a1x); a1y = ffma2(d1, w.y, a1y);
    }
    float4 b4 = *(const float4*)(bb + c4);
    float2 p0 = unpk(a0x), p1 = unpk(a0y), p2 = unpk(a1x), p3 = unpk(a1y);
    float4 o0 = {p0.x + b4.x, p0.y + b4.y, p1.x + b4.z, p1.y + b4.w};
    float4 o1 = {p2.x + b4.x, p2.y + b4.y, p3.x + b4.z, p3.y + b4.w};

    const int gr = row0 + 2 * rp;
    const int b  = gr >> 9, s = gr & 511;
    const int h  = c4 >> 3, dd = c4 & 7;
    if (mat == 1) {   // transposed K: [b,h,dh,s]
        float* base = g_kT + ((b * 8 + h) * 8 + dd) * 512 + s;
        ((float2*)(base        ))[0] = make_float2(o0.x, o1.x);
        ((float2*)(base + 512  ))[0] = make_float2(o0.y, o1.y);
        ((float2*)(base + 1024 ))[0] = make_float2(o0.z, o1.z);
        ((float2*)(base + 1536 ))[0] = make_float2(o0.w, o1.w);
    } else {
        float* dst = ((mat == 0) ? g_q : g_v) + ((b * 8 + h) * 512 + s) * 8 + dd;
        *(float4*)(dst)     = o0;
        *(float4*)(dst + 8) = o1;
    }
}

// ---------------- attention: one (b,h,qtile-of-64) unit ----------------
__device__ __forceinline__ void attn_unit(int unit, float* __restrict__ sm) {
    float* Kt = sm;          // [8][512]
    float* Vs = sm + 4096;   // swizzled [512][8]
    const int bh  = unit >> 3;
    const int qt  = unit & 7;
    const int tid = threadIdx.x;

    {
        const float4* Ksrc = (const float4*)(g_kT + bh * 4096);
        const float4* Vsrc = (const float4*)(g_v  + bh * 4096);
        float4* Kd = (float4*)Kt;
        float4* Vd = (float4*)Vs;
        for (int i = tid; i < 1024; i += 256) {
            Kd[i] = Ksrc[i];
            Vd[i ^ ((i >> 3) & 7)] = Vsrc[i];
        }
    }
    __syncthreads();

    const int qp  = tid >> 3;
    const int seg = tid & 7;
    const int q0  = qt * 64 + 2 * qp;

    u64 qd0[8], qd1[8];
    {
        const float* qg = g_q + (bh * 512 + q0) * 8;
        const float C = 0.35355339059327373f * 1.4426950408889634f; // scale*log2(e)
#pragma unroll
        for (int j = 0; j < 8; j++) {
            qd0[j] = dup2(qg[j] * C);
            qd1[j] = dup2(qg[8 + j] * C);
        }
    }

    float m0 = -1e30f, m1 = -1e30f, l0 = 0.f, l1 = 0.f;
    u64 oa[4] = {0,0,0,0}, ob[4] = {0,0,0,0};

    for (int i = 0; i < 16; i++) {
        const int k4 = seg * 4 + 32 * i;
        u64 sA = 0, sB = 0, sC = 0, sD = 0;
#pragma unroll
        for (int j = 0; j < 8; j++) {
            ulonglong2 kv = *(const ulonglong2*)(Kt + j * 512 + k4);
            sA = ffma2(qd0[j], kv.x, sA);
            sB = ffma2(qd0[j], kv.y, sB);
            sC = ffma2(qd1[j], kv.x, sC);
            sD = ffma2(qd1[j], kv.y, sD);
        }
        float2 fA = unpk(sA), fB = unpk(sB), fC = unpk(sC), fD = unpk(sD);
        float c0 = fmaxf(fmaxf(fA.x, fA.y), fmaxf(fB.x, fB.y));
        float c1 = fmaxf(fmaxf(fC.x, fC.y), fmaxf(fD.x, fD.y));
        if (c0 > m0) {
            float al = ex2f(m0 - c0); l0 *= al; u64 ad = dup2(al);
            oa[0]=mul2(oa[0],ad); oa[1]=mul2(oa[1],ad); oa[2]=mul2(oa[2],ad); oa[3]=mul2(oa[3],ad);
            m0 = c0;
        }
        if (c1 > m1) {
            float al = ex2f(m1 - c1); l1 *= al; u64 ad = dup2(al);
            ob[0]=mul2(ob[0],ad); ob[1]=mul2(ob[1],ad); ob[2]=mul2(ob[2],ad); ob[3]=mul2(ob[3],ad);
            m1 = c1;
        }
        float p0[4], p1[4];
        p0[0]=ex2f(fA.x-m0); p0[1]=ex2f(fA.y-m0); p0[2]=ex2f(fB.x-m0); p0[3]=ex2f(fB.y-m0);
        p1[0]=ex2f(fC.x-m1); p1[1]=ex2f(fC.y-m1); p1[2]=ex2f(fD.x-m1); p1[3]=ex2f(fD.y-m1);
        l0 += (p0[0]+p0[1]) + (p0[2]+p0[3]);
        l1 += (p1[0]+p1[1]) + (p1[2]+p1[3]);
#pragma unroll
        for (int kk = 0; kk < 4; kk++) {
            int k  = k4 + kk;
            int u0 = (2 * k) ^ seg;
            ulonglong2 va = *(const ulonglong2*)(Vs + u0 * 4);
            ulonglong2 vb = *(const ulonglong2*)(Vs + (u0 ^ 1) * 4);
            u64 d0 = dup2(p0[kk]), d1 = dup2(p1[kk]);
            oa[0]=ffma2(d0,va.x,oa[0]); oa[1]=ffma2(d0,va.y,oa[1]);
            oa[2]=ffma2(d0,vb.x,oa[2]); oa[3]=ffma2(d0,vb.y,oa[3]);
            ob[0]=ffma2(d1,va.x,ob[0]); ob[1]=ffma2(d1,va.y,ob[1]);
            ob[2]=ffma2(d1,vb.x,ob[2]); ob[3]=ffma2(d1,vb.y,ob[3]);
        }
    }

    // merge 8 key-segments (lanes qp*8 .. qp*8+7 within warp)
#pragma unroll
    for (int off = 1; off < 8; off <<= 1) {
        float mm0 = __shfl_xor_sync(~0u, m0, off);
        float ll0 = __shfl_xor_sync(~0u, l0, off);
        float mm1 = __shfl_xor_sync(~0u, m1, off);
        float ll1 = __shfl_xor_sync(~0u, l1, off);
        u64 t0[4], t1[4];
#pragma unroll
        for (int j = 0; j < 4; j++) {
            t0[j] = __shfl_xor_sync(~0u, oa[j], off);
            t1[j] = __shfl_xor_sync(~0u, ob[j], off);
        }
        float M0 = fmaxf(m0, mm0), M1 = fmaxf(m1, mm1);
        float a1 = ex2f(m0 - M0), a2 = ex2f(mm0 - M0);
        float b1v = ex2f(m1 - M1), b2v = ex2f(mm1 - M1);
        l0 = l0 * a1 + ll0 * a2;
        l1 = l1 * b1v + ll1 * b2v;
        u64 A1 = dup2(a1), A2 = dup2(a2), B1 = dup2(b1v), B2 = dup2(b2v);
#pragma unroll
        for (int j = 0; j < 4; j++) {
            oa[j] = ffma2(t0[j], A2, mul2(oa[j], A1));
            ob[j] = ffma2(t1[j], B2, mul2(ob[j], B1));
        }
        m0 = M0; m1 = M1;
    }

    if (seg == 0) {
        float inv0 = 1.f / l0, inv1 = 1.f / l1;
        const int b = bh >> 3, h = bh & 7;
        float* op = g_attp + (b * 512 + q0) * 64 + h * 8;
        float2 x0 = unpk(oa[0]), x1 = unpk(oa[1]), x2 = unpk(oa[2]), x3 = unpk(oa[3]);
        ((float4*)op)[0] = make_float4(x0.x*inv0, x0.y*inv0, x1.x*inv0, x1.y*inv0);
        ((float4*)op)[1] = make_float4(x2.x*inv0, x2.y*inv0, x3.x*inv0, x3.y*inv0);
        float2 y0 = unpk(ob[0]), y1 = unpk(ob[1]), y2 = unpk(ob[2]), y3 = unpk(ob[3]);
        float* oq = op + 64;
        ((float4*)oq)[0] = make_float4(y0.x*inv1, y0.y*inv1, y1.x*inv1, y1.y*inv1);
        ((float4*)oq)[1] = make_float4(y2.x*inv1, y2.y*inv1, y3.x*inv1, y3.y*inv1);
    }
    __syncthreads();
}

// ---------------- tail: oproj + FFN + k-write + combine + next QKV ----------------
__device__ __forceinline__ void tail_unit(
        int unit, int st, int step, float* __restrict__ sm,
        float* __restrict__ out,
        const float* __restrict__ Wq, const float* __restrict__ bq,
        const float* __restrict__ Wk, const float* __restrict__ bk,
        const float* __restrict__ Wv, const float* __restrict__ bv,
        const float* __restrict__ Wo, const float* __restrict__ bo,
        const float* __restrict__ W1, const float* __restrict__ b1,
        const float* __restrict__ W2, const float* __restrict__ b2) {
    float* ap   = sm;            // 512
    float* atts = sm + 512;      // 512
    float* z_s  = sm + 1024;     // 512
    float* h_s  = sm + 1536;     // 2048
    float* ysm  = sm + 3584;     // 512

    const int tid = threadIdx.x;
    const int r0  = unit * 8;

    for (int i = tid; i < 128; i += 256)
        ((float4*)ap)[i] = ((const float4*)(g_attp + r0 * 64))[i];
    __syncthreads();

    const int r  = tid >> 5;        // 0..7
    const int kh = (tid >> 4) & 1;  // k-half
    const int cq = tid & 15;
    const int c4 = cq * 4;

    // ---- output projection ----
    {
        u64 ax = 0, ay = 0;
        const float* aprow = ap + r * 64;
        const int k0 = kh * 32;
#pragma unroll 8
        for (int kk = k0; kk < k0 + 32; kk++) {
            ulonglong2 w = *(const ulonglong2*)(Wo + kk * 64 + c4);
            u64 d = dup2(aprow[kk]);
            ax = ffma2(d, w.x, ax);
            ay = ffma2(d, w.y, ay);
        }
        ax = add2(ax, __shfl_xor_sync(~0u, ax, 16));
        ay = add2(ay, __shfl_xor_sync(~0u, ay, 16));
        if (kh == 0) {
            float2 f0 = unpk(ax), f1 = unpk(ay);
            float4 b4 = *(const float4*)(bo + c4);
            float4 a = {f0.x + b4.x, f0.y + b4.y, f1.x + b4.z, f1.y + b4.w};
            *(float4*)(atts + r * 64 + c4) = a;
            float4 ys4 = *(const float4*)(g_ys + (r0 + r) * 64 + c4);
            float4 z = {a.x + ys4.x, a.y + ys4.y, a.z + ys4.z, a.w + ys4.w};
            *(float4*)(z_s + r * 64 + c4) = z;
        }
    }
    __syncthreads();

    // ---- FFN layer 1 ----
    {
        const int cf = (tid & 63) * 4;
        const int rp = tid >> 6;
        u64 a0x = 0, a0y = 0, a1x = 0, a1y = 0;
        const float* z0 = z_s + (2 * rp) * 64;
        const float* z1 = z0 + 64;
#pragma unroll 8
        for (int kk = 0; kk < 64; kk++) {
            ulonglong2 w = *(const ulonglong2*)(W1 + kk * 256 + cf);
            u64 d0 = dup2(z0[kk]), d1 = dup2(z1[kk]);
            a0x = ffma2(d0, w.x, a0x); a0y = ffma2(d0, w.y, a0y);
            a1x = ffma2(d1, w.x, a1x); a1y = ffma2(d1, w.y, a1y);
        }
        float4 b4 = *(const float4*)(b1 + cf);
        float2 u0 = unpk(a0x), u1 = unpk(a0y), u2 = unpk(a1x), u3 = unpk(a1y);
        *(float4*)(h_s + (2 * rp) * 256 + cf) =
            make_float4(fmaxf(u0.x + b4.x, 0.f), fmaxf(u0.y + b4.y, 0.f),
                        fmaxf(u1.x + b4.z, 0.f), fmaxf(u1.y + b4.w, 0.f));
        *(float4*)(h_s + (2 * rp + 1) * 256 + cf) =
            make_float4(fmaxf(u2.x + b4.x, 0.f), fmaxf(u2.y + b4.y, 0.f),
                        fmaxf(u3.x + b4.z, 0.f), fmaxf(u3.y + b4.w, 0.f));
    }
    __syncthreads();

    // ---- FFN layer 2 + residual + RK combine ----
    {
        u64 ax = 0, ay = 0;
        const float* hrow = h_s + r * 256;
        const int k0 = kh * 128;
#pragma unroll 8
        for (int kk = k0; kk < k0 + 128; kk++) {
            ulonglong2 w = *(const ulonglong2*)(W2 + kk * 64 + c4);
            u64 d = dup2(hrow[kk]);
            ax = ffma2(d, w.x, ax);
            ay = ffma2(d, w.y, ay);
        }
        ax = add2(ax, __shfl_xor_sync(~0u, ax, 16));
        ay = add2(ay, __shfl_xor_sync(~0u, ay, 16));
        if (kh == 0) {
            float2 f0 = unpk(ax), f1 = unpk(ay);
            float4 b4  = *(const float4*)(b2 + c4);
            float4 at4 = *(const float4*)(atts + r * 64 + c4);
            float4 kv = {at4.x + f0.x + b4.x, at4.y + f0.y + b4.y,
                         at4.z + f1.x + b4.z, at4.w + f1.y + b4.w};
            const int gi = (r0 + r) * 64 + c4;
            *(float4*)(g_kbuf[st] + gi) = kv;

            float4 y = *(const float4*)(g_y + gi);
            if (st < 5) {
                for (int j = 0; j < st; j++) {
                    float cc = d_C[st + 1][j];
                    float4 kj = *(const float4*)(g_kbuf[j] + gi);
                    y.x = fmaf(cc, kj.x, y.x); y.y = fmaf(cc, kj.y, y.y);
                    y.z = fmaf(cc, kj.z, y.z); y.w = fmaf(cc, kj.w, y.w);
                }
                float cc = d_C[st + 1][st];
                y.x = fmaf(cc, kv.x, y.x); y.y = fmaf(cc, kv.y, y.y);
                y.z = fmaf(cc, kv.z, y.z); y.w = fmaf(cc, kv.w, y.w);
                *(float4*)(g_ys + gi) = y;
                *(float4*)(ysm + r * 64 + c4) = y;
            } else {
                for (int j = 0; j < 5; j++) {
                    float cc = d_B[j];
                    float4 kj = *(const float4*)(g_kbuf[j] + gi);
                    y.x = fmaf(cc, kj.x, y.x); y.y = fmaf(cc, kj.y, y.y);
                    y.z = fmaf(cc, kj.z, y.z); y.w = fmaf(cc, kj.w, y.w);
                }
                float cc = d_B[5];
                y.x = fmaf(cc, kv.x, y.x); y.y = fmaf(cc, kv.y, y.y);
                y.z = fmaf(cc, kv.z, y.z); y.w = fmaf(cc, kv.w, y.w);
                if (step == 3) {
                    *(float4*)(out + gi) = y;
                } else {
                    *(float4*)(g_y  + gi) = y;
                    *(float4*)(g_ys + gi) = y;
                    *(float4*)(ysm + r * 64 + c4) = y;
                }
            }
        }
    }
    __syncthreads();
    if (!(st == 5 && step == 3))
        qkv_from_smem(ysm, r0, Wq, bq, Wk, bk, Wv, bv);
    __syncthreads();
}

// ---------------- persistent kernel ----------------
__global__ void __launch_bounds__(256, 2)
fused_ode_kernel(const float* __restrict__ x, float* __restrict__ out,
                 const float* __restrict__ Wq, const float* __restrict__ bq,
                 const float* __restrict__ Wk, const float* __restrict__ bk,
                 const float* __restrict__ Wv, const float* __restrict__ bv,
                 const float* __restrict__ Wo, const float* __restrict__ bo,
                 const float* __restrict__ W1, const float* __restrict__ b1,
                 const float* __restrict__ W2, const float* __restrict__ b2) {
    __shared__ float sm[8192];
    unsigned gen = g_gen;
    const int tid = threadIdx.x;
    const unsigned nblk = gridDim.x;

    for (int unit = blockIdx.x; unit < 256; unit += nblk) {
        const int r0 = unit * 8;
        for (int i = tid; i < 128; i += 256) {
            float4 v = ((const float4*)(x + r0 * 64))[i];
            ((float4*)(g_y  + r0 * 64))[i] = v;
            ((float4*)(g_ys + r0 * 64))[i] = v;
            ((float4*)sm)[i] = v;
        }
        __syncthreads();
        qkv_from_smem(sm, r0, Wq, bq, Wk, bk, Wv, bv);
        __syncthreads();
    }
    gsync(gen);

    for (int step = 0; step < 4; ++step) {
        for (int st = 0; st < 6; ++st) {
            for (int unit = blockIdx.x; unit < 256; unit += nblk)
                attn_unit(unit, sm);
            gsync(gen);
            for (int unit = blockIdx.x; unit < 256; unit += nblk)
                tail_unit(unit, st, step, sm, out,
                          Wq, bq, Wk, bk, Wv, bv, Wo, bo, W1, b1, W2, b2);
            if (!(step == 3 && st == 5)) gsync(gen);
        }
    }
}

// ---------------- host launcher ----------------
extern "C" void kernel_launch(void* const* d_in, const int* in_sizes, int n_in,
                              void* d_out, int out_size) {
    const float* x  = (const float*)d_in[0];
    // d_in[1] = mask: additive [B,1,S,1] broadcast over key axis -> softmax no-op
    const float* Wq = (const float*)d_in[2];
    const float* bq = (const float*)d_in[3];
    const float* Wk = (const float*)d_in[4];
    const float* bk = (const float*)d_in[5];
    const float* Wv = (const float*)d_in[6];
    const float* bv = (const float*)d_in[7];
    const float* Wo = (const float*)d_in[8];
    const float* bo = (const float*)d_in[9];
    const float* W1 = (const float*)d_in[10];
    const float* b1 = (const float*)d_in[11];
    const float* W2 = (const float*)d_in[12];
    const float* b2 = (const float*)d_in[13];
    float* out = (float*)d_out;

    int dev = 0, sms = 148;
    cudaGetDevice(&dev);
    cudaDeviceGetAttribute(&sms, cudaDevAttrMultiProcessorCount, dev);
    int nblk = sms * 2;
    if (nblk > 512) nblk = 512;

    fused_ode_kernel<<<nblk, 256>>>(x, out,
                                    Wq, bq, Wk, bk, Wv, bv,
                                    Wo, bo, W1, b1, W2, b2);
}

// round 6
// speedup vs baseline: 1.2180x; 1.2180x over previous
#include <cuda_runtime.h>

#define SEQ    512
#define NROW   2048
#define NPAIR  1024
#define NELEM  (NROW*64)

typedef unsigned long long u64;

// ---------------- f32x2 helpers ----------------
__device__ __forceinline__ u64 ffma2(u64 a, u64 b, u64 c) {
    u64 d; asm("fma.rn.f32x2 %0, %1, %2, %3;" : "=l"(d) : "l"(a), "l"(b), "l"(c)); return d;
}
__device__ __forceinline__ u64 mul2(u64 a, u64 b) {
    u64 d; asm("mul.rn.f32x2 %0, %1, %2;" : "=l"(d) : "l"(a), "l"(b)); return d;
}
__device__ __forceinline__ u64 add2(u64 a, u64 b) {
    u64 d; asm("add.rn.f32x2 %0, %1, %2;" : "=l"(d) : "l"(a), "l"(b)); return d;
}
__device__ __forceinline__ u64 dup2(float x) {
    u64 d; asm("mov.b64 %0, {%1, %1};" : "=l"(d) : "f"(x)); return d;
}
__device__ __forceinline__ u64 pack2(float x, float y) {
    u64 d; asm("mov.b64 %0, {%1, %2};" : "=l"(d) : "f"(x), "f"(y)); return d;
}
__device__ __forceinline__ float2 unpk(u64 a) {
    float2 f; asm("mov.b64 {%0, %1}, %2;" : "=f"(f.x), "=f"(f.y) : "l"(a)); return f;
}
__device__ __forceinline__ float ex2f(float x) {
    float r; asm("ex2.approx.f32 %0, %1;" : "=f"(r) : "f"(x)); return r;
}
__device__ __forceinline__ u64 relu2(u64 a) {
    float2 f = unpk(a); return pack2(fmaxf(f.x, 0.f), fmaxf(f.y, 0.f));
}

// ---------------- device scratch ----------------
__device__ float g_q [NELEM];          // [B,H,S,8]
__device__ float g_kT[NELEM];          // [B,H,8,S]
__device__ float g_v [NELEM];          // [B,H,S,8]
__device__ u64 g_yp [NPAIR*64];        // y  packed: [pair][col]
__device__ u64 g_ysp[NPAIR*64];        // ys packed
__device__ u64 g_kp [6][NPAIR*64];     // k stages packed
__device__ u64 g_app[NPAIR*64];        // attn out packed [pair][h*8+d]

__device__ unsigned          g_cnt;
__device__ volatile unsigned g_gen;

__constant__ float d_C[6][5] = {
    {0.f,0.f,0.f,0.f,0.f},
    {(float)(0.25*0.25), 0.f,0.f,0.f,0.f},
    {(float)(0.25*3.0/32.0), (float)(0.25*9.0/32.0), 0.f,0.f,0.f},
    {(float)(0.25*1932.0/2197.0), (float)(0.25*-7200.0/2197.0),
     (float)(0.25*7296.0/2197.0), 0.f,0.f},
    {(float)(0.25*439.0/216.0), (float)(0.25*-8.0),
     (float)(0.25*3680.0/513.0), (float)(0.25*-845.0/4104.0), 0.f},
    {(float)(0.25*-8.0/27.0), (float)(0.25*2.0),
     (float)(0.25*-3544.0/2565.0), (float)(0.25*1859.0/4104.0),
     (float)(0.25*-11.0/40.0)}
};
__constant__ float d_B[6] = {
    (float)(0.25*16.0/135.0), 0.f,
    (float)(0.25*6656.0/12825.0),
    (float)(0.25*28561.0/56430.0),
    (float)(0.25*-9.0/50.0),
    (float)(0.25*2.0/55.0)
};

// ---------------- grid barrier ----------------
__device__ __forceinline__ void gsync(unsigned& gen) {
    __syncthreads();
    if (threadIdx.x == 0) {
        __threadfence();
        if (atomicAdd(&g_cnt, 1u) == gridDim.x - 1) {
            g_cnt = 0;
            __threadfence();
            g_gen = gen + 1;
        } else {
            while (g_gen == gen) { }
            __threadfence();
        }
    }
    __syncthreads();
    gen++;
}

// ---------------- packed GEMM partial ----------------
// acc[cl*2+pr]: cl = weight col offset (0..3), pr = pair within this thread's
// pair-group (rows 2*pq2+pr of the unit).
__device__ __forceinline__ void gemm_partial(
        const float* __restrict__ W, int wstride, int colbase,
        const u64* __restrict__ act, int rowlen, int pq2,
        int k0, int kn, u64* acc) {
    const u64* a0 = act + (2 * pq2) * rowlen;
    const u64* a1 = a0 + rowlen;
#pragma unroll 4
    for (int k = k0; k < k0 + kn; k++) {
        float4 w = *(const float4*)(W + k * wstride + colbase);
        u64 z0 = a0[k], z1 = a1[k];
        u64 w0 = dup2(w.x), w1 = dup2(w.y), w2 = dup2(w.z), w3 = dup2(w.w);
        acc[0] = ffma2(z0, w0, acc[0]); acc[1] = ffma2(z1, w0, acc[1]);
        acc[2] = ffma2(z0, w1, acc[2]); acc[3] = ffma2(z1, w1, acc[3]);
        acc[4] = ffma2(z0, w2, acc[4]); acc[5] = ffma2(z1, w2, acc[5]);
        acc[6] = ffma2(z0, w3, acc[6]); acc[7] = ffma2(z1, w3, acc[7]);
    }
}

// 8-way k-group gather for 64-col GEMMs (writers tid = c4 + 16*pq2 + 32*kq)
__device__ __forceinline__ u64 gather8(const u64* __restrict__ red, int base, int j) {
    u64 s = red[base * 9 + j];
#pragma unroll
    for (int kq = 1; kq < 8; kq++)
        s = add2(s, red[(base + 32 * kq) * 9 + j]);
    return s;
}

// ---------------- QKV: 3 sequential 64-col GEMMs from packed ys ----------------
__device__ __forceinline__ void qkv_mats(
        int unit, const u64* __restrict__ ys_p, u64* __restrict__ red,
        const float* __restrict__ Wq, const float* __restrict__ bq,
        const float* __restrict__ Wk, const float* __restrict__ bk,
        const float* __restrict__ Wv, const float* __restrict__ bv) {
    const int tid = threadIdx.x;
    const int c4 = tid & 15, pq2 = (tid >> 4) & 1, kq = tid >> 5;
    const int fc = tid & 63, fp = tid >> 6;
    const int row0 = unit * 8 + 2 * fp;
    const int b = row0 >> 9, s = row0 & 511;
    const int h = fc >> 3, dd = fc & 7;
    const int gbase = (fc >> 2) + 16 * (fp >> 1);
    const int gj = (fc & 3) * 2 + (fp & 1);

#pragma unroll
    for (int mat = 0; mat < 3; mat++) {
        const float* W  = mat == 0 ? Wq : mat == 1 ? Wk : Wv;
        const float* bb = mat == 0 ? bq : mat == 1 ? bk : bv;
        u64 acc[8] = {0,0,0,0,0,0,0,0};
        gemm_partial(W, 64, c4 * 4, ys_p, 64, pq2, kq * 8, 8, acc);
        __syncthreads();           // red free from previous readers
#pragma unroll
        for (int j = 0; j < 8; j++) red[tid * 9 + j] = acc[j];
        __syncthreads();
        u64 v = gather8(red, gbase, gj);
        v = add2(v, dup2(bb[fc]));
        float2 q2 = unpk(v);       // (row s, row s+1)
        if (mat == 1) {
            *(float2*)(g_kT + ((b * 8 + h) * 8 + dd) * 512 + s) = make_float2(q2.x, q2.y);
        } else {
            float* dst = (mat == 0 ? g_q : g_v) + ((b * 8 + h) * 512 + s) * 8 + dd;
            dst[0] = q2.x; dst[8] = q2.y;
        }
    }
}

// ---------------- attention: one (b,h,qtile-of-64) unit ----------------
__device__ __forceinline__ void attn_unit(int unit, float* __restrict__ sm) {
    float* Kt = sm;          // [8][512]
    float* Vs = sm + 4096;   // swizzled [512][8]
    const int bh  = unit >> 3;
    const int qt  = unit & 7;
    const int tid = threadIdx.x;

    {
        const float4* Ksrc = (const float4*)(g_kT + bh * 4096);
        const float4* Vsrc = (const float4*)(g_v  + bh * 4096);
        float4* Kd = (float4*)Kt;
        float4* Vd = (float4*)Vs;
        for (int i = tid; i < 1024; i += 256) {
            Kd[i] = Ksrc[i];
            Vd[i ^ ((i >> 3) & 7)] = Vsrc[i];
        }
    }
    __syncthreads();

    const int qp  = tid >> 3;
    const int seg = tid & 7;
    const int q0  = qt * 64 + 2 * qp;

    u64 qd0[8], qd1[8];
    {
        const float* qg = g_q + (bh * 512 + q0) * 8;
        const float C = 0.35355339059327373f * 1.4426950408889634f;
#pragma unroll
        for (int j = 0; j < 8; j++) {
            qd0[j] = dup2(qg[j] * C);
            qd1[j] = dup2(qg[8 + j] * C);
        }
    }

    float m0 = -1e30f, m1 = -1e30f, l0 = 0.f, l1 = 0.f;
    u64 oa[4] = {0,0,0,0}, ob[4] = {0,0,0,0};

    for (int i = 0; i < 16; i++) {
        const int k4 = seg * 4 + 32 * i;
        u64 sA = 0, sB = 0, sC = 0, sD = 0;
#pragma unroll
        for (int j = 0; j < 8; j++) {
            ulonglong2 kv = *(const ulonglong2*)(Kt + j * 512 + k4);
            sA = ffma2(qd0[j], kv.x, sA);
            sB = ffma2(qd0[j], kv.y, sB);
            sC = ffma2(qd1[j], kv.x, sC);
            sD = ffma2(qd1[j], kv.y, sD);
        }
        float2 fA = unpk(sA), fB = unpk(sB), fC = unpk(sC), fD = unpk(sD);
        float c0 = fmaxf(fmaxf(fA.x, fA.y), fmaxf(fB.x, fB.y));
        float c1 = fmaxf(fmaxf(fC.x, fC.y), fmaxf(fD.x, fD.y));
        if (c0 > m0) {
            float al = ex2f(m0 - c0); l0 *= al; u64 ad = dup2(al);
            oa[0]=mul2(oa[0],ad); oa[1]=mul2(oa[1],ad); oa[2]=mul2(oa[2],ad); oa[3]=mul2(oa[3],ad);
            m0 = c0;
        }
        if (c1 > m1) {
            float al = ex2f(m1 - c1); l1 *= al; u64 ad = dup2(al);
            ob[0]=mul2(ob[0],ad); ob[1]=mul2(ob[1],ad); ob[2]=mul2(ob[2],ad); ob[3]=mul2(ob[3],ad);
            m1 = c1;
        }
        float p0[4], p1[4];
        p0[0]=ex2f(fA.x-m0); p0[1]=ex2f(fA.y-m0); p0[2]=ex2f(fB.x-m0); p0[3]=ex2f(fB.y-m0);
        p1[0]=ex2f(fC.x-m1); p1[1]=ex2f(fC.y-m1); p1[2]=ex2f(fD.x-m1); p1[3]=ex2f(fD.y-m1);
        l0 += (p0[0]+p0[1]) + (p0[2]+p0[3]);
        l1 += (p1[0]+p1[1]) + (p1[2]+p1[3]);
#pragma unroll
        for (int kk = 0; kk < 4; kk++) {
            int k  = k4 + kk;
            int u0 = (2 * k) ^ seg;
            ulonglong2 va = *(const ulonglong2*)(Vs + u0 * 4);
            ulonglong2 vb = *(const ulonglong2*)(Vs + (u0 ^ 1) * 4);
            u64 d0 = dup2(p0[kk]), d1 = dup2(p1[kk]);
            oa[0]=ffma2(d0,va.x,oa[0]); oa[1]=ffma2(d0,va.y,oa[1]);
            oa[2]=ffma2(d0,vb.x,oa[2]); oa[3]=ffma2(d0,vb.y,oa[3]);
            ob[0]=ffma2(d1,va.x,ob[0]); ob[1]=ffma2(d1,va.y,ob[1]);
            ob[2]=ffma2(d1,vb.x,ob[2]); ob[3]=ffma2(d1,vb.y,ob[3]);
        }
    }

#pragma unroll
    for (int off = 1; off < 8; off <<= 1) {
        float mm0 = __shfl_xor_sync(~0u, m0, off);
        float ll0 = __shfl_xor_sync(~0u, l0, off);
        float mm1 = __shfl_xor_sync(~0u, m1, off);
        float ll1 = __shfl_xor_sync(~0u, l1, off);
        u64 t0[4], t1[4];
#pragma unroll
        for (int j = 0; j < 4; j++) {
            t0[j] = __shfl_xor_sync(~0u, oa[j], off);
            t1[j] = __shfl_xor_sync(~0u, ob[j], off);
        }
        float M0 = fmaxf(m0, mm0), M1 = fmaxf(m1, mm1);
        float a1 = ex2f(m0 - M0), a2 = ex2f(mm0 - M0);
        float b1v = ex2f(m1 - M1), b2v = ex2f(mm1 - M1);
        l0 = l0 * a1 + ll0 * a2;
        l1 = l1 * b1v + ll1 * b2v;
        u64 A1 = dup2(a1), A2 = dup2(a2), B1 = dup2(b1v), B2 = dup2(b2v);
#pragma unroll
        for (int j = 0; j < 4; j++) {
            oa[j] = ffma2(t0[j], A2, mul2(oa[j], A1));
            ob[j] = ffma2(t1[j], B2, mul2(ob[j], B1));
        }
        m0 = M0; m1 = M1;
    }

    if (seg == 0) {
        float inv0 = 1.f / l0, inv1 = 1.f / l1;
        const int b = bh >> 3, h = bh & 7;
        const int gp = (b * 512 + q0) >> 1;
        u64* op = g_app + gp * 64 + h * 8;
#pragma unroll
        for (int j = 0; j < 4; j++) {
            float2 a  = unpk(oa[j]);   // (d=2j, d=2j+1) of row q0
            float2 bb = unpk(ob[j]);   // row q0+1
            op[2 * j]     = pack2(a.x * inv0, bb.x * inv1);
            op[2 * j + 1] = pack2(a.y * inv0, bb.y * inv1);
        }
    }
    __syncthreads();
}

// ---------------- tail: oproj + FFN + RK combine + next QKV (8 rows) --------
__device__ __forceinline__ void tail_unit(
        int unit, int st, int step, u64* __restrict__ sm64,
        float* __restrict__ out,
        const float* __restrict__ Wq, const float* __restrict__ bq,
        const float* __restrict__ Wk, const float* __restrict__ bk,
        const float* __restrict__ Wv, const float* __restrict__ bv,
        const float* __restrict__ Wo, const float* __restrict__ bo,
        const float* __restrict__ W1, const float* __restrict__ b1,
        const float* __restrict__ W2, const float* __restrict__ b2) {
    u64* app_p  = sm64;          // 256
    u64* atts_p = sm64 + 256;    // 256
    u64* z_p    = sm64 + 512;    // 256
    u64* ys_p   = sm64 + 768;    // 256
    u64* h_p    = sm64 + 1024;   // 1024
    u64* red    = sm64 + 2048;   // 2304 (256*9)

    const int tid = threadIdx.x;
    const int c4 = tid & 15, pq2 = (tid >> 4) & 1, kq = tid >> 5;
    const int fc = tid & 63, fp = tid >> 6;
    const int gbase = (fc >> 2) + 16 * (fp >> 1);
    const int gj = (fc & 3) * 2 + (fp & 1);
    const int idx = unit * 256 + tid;   // == (unit*4+fp)*64 + fc

    // 1. load packed attention output
    if (tid < 128)
        ((ulonglong2*)app_p)[tid] = ((const ulonglong2*)(g_app + unit * 256))[tid];
    __syncthreads();

    // 2. output projection
    {
        u64 acc[8] = {0,0,0,0,0,0,0,0};
        gemm_partial(Wo, 64, c4 * 4, app_p, 64, pq2, kq * 8, 8, acc);
#pragma unroll
        for (int j = 0; j < 8; j++) red[tid * 9 + j] = acc[j];
        __syncthreads();
        u64 att = gather8(red, gbase, gj);
        att = add2(att, dup2(bo[fc]));
        atts_p[tid] = att;
        z_p[tid] = add2(att, g_ysp[idx]);
        __syncthreads();
    }

    // 3. FFN layer 1 (cols 256)
    {
        const int pq2b = fp & 1, kqb = fp >> 1;   // fc = col-group
        u64 acc[8] = {0,0,0,0,0,0,0,0};
        gemm_partial(W1, 256, fc * 4, z_p, 64, pq2b, kqb * 32, 32, acc);
        __syncthreads();           // oproj gather readers done (sync above)
#pragma unroll
        for (int j = 0; j < 8; j++) red[tid * 9 + j] = acc[j];
        __syncthreads();
        // final: thread owns cols fc*4..+3 of pair fp
        const int wb = fc + 64 * (fp >> 1);
#pragma unroll
        for (int cl = 0; cl < 4; cl++) {
            int c = fc * 4 + cl;
            int jj = cl * 2 + (fp & 1);
            u64 hv = add2(red[wb * 9 + jj], red[(wb + 128) * 9 + jj]);
            hv = add2(hv, dup2(b1[c]));
            h_p[fp * 256 + c] = relu2(hv);
        }
        __syncthreads();
    }

    // 4. FFN layer 2 + residual + RK combine
    {
        u64 acc[8] = {0,0,0,0,0,0,0,0};
        gemm_partial(W2, 64, c4 * 4, h_p, 256, pq2, kq * 32, 32, acc);
        __syncthreads();           // ffn1 gather readers done
#pragma unroll
        for (int j = 0; j < 8; j++) red[tid * 9 + j] = acc[j];
        __syncthreads();
        u64 kv = gather8(red, gbase, gj);
        kv = add2(kv, dup2(b2[fc]));
        kv = add2(kv, atts_p[tid]);
        g_kp[st][idx] = kv;

        u64 y = g_yp[idx];
        if (st < 5) {
            for (int j = 0; j < st; j++)
                y = ffma2(dup2(d_C[st + 1][j]), g_kp[j][idx], y);
            y = ffma2(dup2(d_C[st + 1][st]), kv, y);
            g_ysp[idx] = y;
            ys_p[tid] = y;
        } else {
#pragma unroll
            for (int j = 0; j < 5; j++)
                y = ffma2(dup2(d_B[j]), g_kp[j][idx], y);
            y = ffma2(dup2(d_B[5]), kv, y);
            if (step == 3) {
                float2 f2 = unpk(y);
                int r = unit * 8 + 2 * fp;
                out[r * 64 + fc]       = f2.x;
                out[(r + 1) * 64 + fc] = f2.y;
            } else {
                g_yp[idx] = y; g_ysp[idx] = y;
                ys_p[tid] = y;
            }
        }
        __syncthreads();
    }

    // 5. next-stage QKV
    if (!(st == 5 && step == 3))
        qkv_mats(unit, ys_p, red, Wq, bq, Wk, bk, Wv, bv);
    __syncthreads();
}

// ---------------- persistent kernel ----------------
__global__ void __launch_bounds__(256, 2)
fused_ode_kernel(const float* __restrict__ x, float* __restrict__ out,
                 const float* __restrict__ Wq, const float* __restrict__ bq,
                 const float* __restrict__ Wk, const float* __restrict__ bk,
                 const float* __restrict__ Wv, const float* __restrict__ bv,
                 const float* __restrict__ Wo, const float* __restrict__ bo,
                 const float* __restrict__ W1, const float* __restrict__ b1,
                 const float* __restrict__ W2, const float* __restrict__ b2) {
    __shared__ u64 sm64[4352];   // 34 KB, reused across phases
    unsigned gen = g_gen;
    const int tid = threadIdx.x;
    const unsigned nblk = gridDim.x;

    // init: y = ys = x (packed), first QKV
    for (int unit = blockIdx.x; unit < 256; unit += nblk) {
        float* xs = (float*)sm64;
        for (int i = tid; i < 128; i += 256)
            ((float4*)xs)[i] = ((const float4*)(x + unit * 512))[i];
        __syncthreads();
        {
            int p = tid >> 6, c = tid & 63;
            u64 u = pack2(xs[2 * p * 64 + c], xs[(2 * p + 1) * 64 + c]);
            __syncthreads();
            int idx = unit * 256 + tid;
            g_yp[idx] = u; g_ysp[idx] = u;
            (sm64 + 768)[tid] = u;
        }
        __syncthreads();
        qkv_mats(unit, sm64 + 768, sm64 + 2048, Wq, bq, Wk, bk, Wv, bv);
        __syncthreads();
    }
    gsync(gen);

    for (int step = 0; step < 4; ++step) {
        for (int st = 0; st < 6; ++st) {
            for (int unit = blockIdx.x; unit < 256; unit += nblk)
                attn_unit(unit, (float*)sm64);
            gsync(gen);
            for (int unit = blockIdx.x; unit < 256; unit += nblk)
                tail_unit(unit, st, step, sm64, out,
                          Wq, bq, Wk, bk, Wv, bv, Wo, bo, W1, b1, W2, b2);
            if (!(step == 3 && st == 5)) gsync(gen);
        }
    }
}

// ---------------- host launcher ----------------
extern "C" void kernel_launch(void* const* d_in, const int* in_sizes, int n_in,
                              void* d_out, int out_size) {
    const float* x  = (const float*)d_in[0];
    // d_in[1] = mask: additive [B,1,S,1] broadcast over key axis -> softmax no-op
    const float* Wq = (const float*)d_in[2];
    const float* bq = (const float*)d_in[3];
    const float* Wk = (const float*)d_in[4];
    const float* bk = (const float*)d_in[5];
    const float* Wv = (const float*)d_in[6];
    const float* bv = (const float*)d_in[7];
    const float* Wo = (const float*)d_in[8];
    const float* bo = (const float*)d_in[9];
    const float* W1 = (const float*)d_in[10];
    const float* b1 = (const float*)d_in[11];
    const float* W2 = (const float*)d_in[12];
    const float* b2 = (const float*)d_in[13];
    float* out = (float*)d_out;

    int dev = 0, sms = 148;
    cudaGetDevice(&dev);
    cudaDeviceGetAttribute(&sms, cudaDevAttrMultiProcessorCount, dev);
    int nblk = sms * 2;
    if (nblk > 512) nblk = 512;

    fused_ode_kernel<<<nblk, 256>>>(x, out,
                                    Wq, bq, Wk, bk, Wv, bv,
                                    Wo, bo, W1, b1, W2, b2);
}